// round 4
// baseline (speedup 1.0000x reference)
#include <cuda_runtime.h>

#define CDIM 1024
#define BB   4
#define TT   2048
#define NH   16
#define HD   64
#define MROWS (BB*TT)   // 8192

// Scratch (allocation-free rule: __device__ globals)
__device__ float g_Q[(size_t)BB*NH*TT*HD];   // [B,H,T,D]
__device__ float g_K[(size_t)BB*NH*TT*HD];
__device__ float g_V[(size_t)BB*NH*TT*HD];
__device__ float g_ctx[(size_t)MROWS*CDIM];  // [B,T,C] attention output

// ---------------------------------------------------------------------------
// NT GEMM: C[m,n] = sum_k A[m,k] * W[n,k]   (both K-contiguous row-major)
// 128x128x16 tile, 256 threads, 8x8 per-thread microtile.
// MODE 0: A = x, K=CDIM, N=3*CDIM; epilogue scatters into g_Q/g_K/g_V [B,H,T,D]
// MODE 1: A = g_ctx, K=CDIM, N=CDIM; epilogue writes C row-major (final output)
// ---------------------------------------------------------------------------
template<int MODE>
__global__ __launch_bounds__(256)
void gemm_nt_kernel(const float* __restrict__ Ain, const float* __restrict__ W,
                    float* __restrict__ C)
{
    __shared__ float As[16][128];
    __shared__ float Bs[16][128];

    const float* A = (MODE == 1) ? (const float*)g_ctx : Ain;
    const int K = CDIM;

    const int tid = threadIdx.x;
    const int tx = tid & 15;
    const int ty = tid >> 4;
    const int m0 = blockIdx.y * 128;
    const int n0 = blockIdx.x * 128;

    float acc[8][8];
    #pragma unroll
    for (int i = 0; i < 8; i++)
        #pragma unroll
        for (int j = 0; j < 8; j++) acc[i][j] = 0.f;

    for (int kt = 0; kt < K; kt += 16) {
        #pragma unroll
        for (int rep = 0; rep < 2; ++rep) {
            int idx = tid + rep * 256;      // float4 index within 128x16 tile
            int r   = idx >> 2;             // 0..127 tile row
            int c4  = idx & 3;              // 0..3 float4 within row
            float4 av = *(const float4*)(A + (size_t)(m0 + r) * K + kt + c4 * 4);
            float4 bv = *(const float4*)(W + (size_t)(n0 + r) * K + kt + c4 * 4);
            As[c4*4+0][r] = av.x; As[c4*4+1][r] = av.y;
            As[c4*4+2][r] = av.z; As[c4*4+3][r] = av.w;
            Bs[c4*4+0][r] = bv.x; Bs[c4*4+1][r] = bv.y;
            Bs[c4*4+2][r] = bv.z; Bs[c4*4+3][r] = bv.w;
        }
        __syncthreads();
        #pragma unroll
        for (int kk = 0; kk < 16; ++kk) {
            float a[8], b[8];
            #pragma unroll
            for (int i = 0; i < 8; i++) a[i] = As[kk][ty*8 + i];
            #pragma unroll
            for (int j = 0; j < 8; j++) b[j] = Bs[kk][tx*8 + j];
            #pragma unroll
            for (int i = 0; i < 8; i++)
                #pragma unroll
                for (int j = 0; j < 8; j++)
                    acc[i][j] = fmaf(a[i], b[j], acc[i][j]);
        }
        __syncthreads();
    }

    #pragma unroll
    for (int i = 0; i < 8; i++) {
        int m = m0 + ty*8 + i;
        int b = m >> 11;            // /TT
        int t = m & (TT - 1);
        #pragma unroll
        for (int j = 0; j < 8; j++) {
            int n = n0 + tx*8 + j;
            float v = acc[i][j];
            if (MODE == 0) {
                int part = n >> 10;          // 0=q 1=k 2=v
                int c    = n & (CDIM - 1);
                int h    = c >> 6;
                int d    = c & 63;
                size_t o = (((size_t)(b*NH + h))*TT + t)*HD + d;
                if (part == 0)      g_Q[o] = v;
                else if (part == 1) g_K[o] = v;
                else                g_V[o] = v;
            } else {
                C[(size_t)m * CDIM + n] = v;
            }
        }
    }
}

// ---------------------------------------------------------------------------
// Causal flash-style attention, fp32.
// grid = (T/128 q-tiles, B*H). 128 threads/block; each thread owns ONE query
// row: q (64 regs) and O accumulator (64 regs), m/l scalars -> no cross-thread
// reductions at all. K/V tiles (64 rows) + per-thread S row live in dyn smem.
// Causal handled by tile-skip (only 2*qt+2 K-tiles) + mask on diagonal tiles.
// ---------------------------------------------------------------------------
__global__ __launch_bounds__(128)
void attn_kernel()
{
    extern __shared__ float smem[];
    float* Ks = smem;            // 64*64
    float* Vs = smem + 4096;     // 64*64
    float* Ss = smem + 8192;     // [64][128]  (j-major: conflict-free)

    const int tid = threadIdx.x;
    const int qt  = (int)gridDim.x - 1 - (int)blockIdx.x;  // heavy tiles first
    const int bh  = blockIdx.y;
    const int qg  = qt * 128 + tid;

    const float scale = 0.125f;   // 1/sqrt(64)
    const float4* Qp = (const float4*)(g_Q + ((size_t)bh * TT + qg) * HD);
    float4 q[16];
    #pragma unroll
    for (int i = 0; i < 16; i++) {
        float4 t = Qp[i];
        t.x *= scale; t.y *= scale; t.z *= scale; t.w *= scale;
        q[i] = t;
    }

    float O[64];
    #pragma unroll
    for (int i = 0; i < 64; i++) O[i] = 0.f;
    float mrow = -1e30f, lrow = 0.f;

    const float* Kb = g_K + (size_t)bh * TT * HD;
    const float* Vb = g_V + (size_t)bh * TT * HD;
    const int ntiles = 2*qt + 2;

    for (int jt = 0; jt < ntiles; ++jt) {
        const int j0 = jt * 64;
        __syncthreads();
        // K/V tiles are fully contiguous (rows j0..j0+63 x 64 floats) -> linear copy
        const float4* Kg = (const float4*)(Kb + (size_t)j0 * HD);
        const float4* Vg = (const float4*)(Vb + (size_t)j0 * HD);
        #pragma unroll
        for (int r = 0; r < 8; r++) {
            ((float4*)Ks)[tid + r*128] = Kg[tid + r*128];
            ((float4*)Vs)[tid + r*128] = Vg[tid + r*128];
        }
        __syncthreads();

        // S = q . K^T   (smem K reads are warp-uniform -> broadcast)
        float tmax = -1e30f;
        #pragma unroll 2
        for (int j = 0; j < 64; j++) {
            const float4* kr = (const float4*)(Ks + j * HD);
            float s0 = 0.f, s1 = 0.f, s2 = 0.f, s3 = 0.f;
            #pragma unroll
            for (int i = 0; i < 16; i += 4) {
                float4 k0 = kr[i],   k1 = kr[i+1];
                float4 k2 = kr[i+2], k3 = kr[i+3];
                s0 = fmaf(q[i  ].x,k0.x, fmaf(q[i  ].y,k0.y, fmaf(q[i  ].z,k0.z, fmaf(q[i  ].w,k0.w, s0))));
                s1 = fmaf(q[i+1].x,k1.x, fmaf(q[i+1].y,k1.y, fmaf(q[i+1].z,k1.z, fmaf(q[i+1].w,k1.w, s1))));
                s2 = fmaf(q[i+2].x,k2.x, fmaf(q[i+2].y,k2.y, fmaf(q[i+2].z,k2.z, fmaf(q[i+2].w,k2.w, s2))));
                s3 = fmaf(q[i+3].x,k3.x, fmaf(q[i+3].y,k3.y, fmaf(q[i+3].z,k3.z, fmaf(q[i+3].w,k3.w, s3))));
            }
            float s = (s0 + s1) + (s2 + s3);
            if (j0 + j > qg) s = -1e30f;     // causal mask (diagonal tiles)
            Ss[j*128 + tid] = s;
            tmax = fmaxf(tmax, s);
        }

        // online softmax rescale
        float mnew  = fmaxf(mrow, tmax);
        float alpha = __expf(mrow - mnew);
        mrow = mnew;
        lrow *= alpha;
        #pragma unroll
        for (int i = 0; i < 64; i++) O[i] *= alpha;

        // P = exp(S - m); O += P @ V
        #pragma unroll 2
        for (int j = 0; j < 64; j++) {
            float p = __expf(Ss[j*128 + tid] - mnew);
            lrow += p;
            const float4* vr = (const float4*)(Vs + j * HD);
            #pragma unroll
            for (int i = 0; i < 16; i++) {
                float4 vv = vr[i];
                O[4*i+0] = fmaf(p, vv.x, O[4*i+0]);
                O[4*i+1] = fmaf(p, vv.y, O[4*i+1]);
                O[4*i+2] = fmaf(p, vv.z, O[4*i+2]);
                O[4*i+3] = fmaf(p, vv.w, O[4*i+3]);
            }
        }
    }

    const float inv = 1.0f / lrow;
    const int b = bh >> 4, h = bh & 15;
    float4* outp = (float4*)(g_ctx + ((size_t)(b*TT + qg)) * CDIM + h * HD);
    #pragma unroll
    for (int i = 0; i < 16; i++) {
        float4 o;
        o.x = O[4*i+0]*inv; o.y = O[4*i+1]*inv;
        o.z = O[4*i+2]*inv; o.w = O[4*i+3]*inv;
        outp[i] = o;
    }
}

// ---------------------------------------------------------------------------
extern "C" void kernel_launch(void* const* d_in, const int* in_sizes, int n_in,
                              void* d_out, int out_size)
{
    const float* x      = (const float*)d_in[0];  // [4,2048,1024]
    const float* w_qkv  = (const float*)d_in[1];  // [3072,1024]
    const float* w_proj = (const float*)d_in[2];  // [1024,1024]
    float* out = (float*)d_out;                   // [4,2048,1024]

    // attention needs 64 KB dynamic smem (> 48 KB default)
    cudaFuncSetAttribute(attn_kernel,
                         cudaFuncAttributeMaxDynamicSharedMemorySize, 65536);

    // 1) QKV projection + scatter to [B,H,T,D]
    gemm_nt_kernel<0><<<dim3(3*CDIM/128, MROWS/128), 256>>>(x, w_qkv, nullptr);

    // 2) causal attention -> g_ctx [B,T,C]
    attn_kernel<<<dim3(TT/128, BB*NH), 128, 65536>>>();

    // 3) output projection -> d_out
    gemm_nt_kernel<1><<<dim3(CDIM/128, MROWS/128), 256>>>(nullptr, w_proj, out);
}

// round 6
// speedup vs baseline: 1.6597x; 1.6597x over previous
#include <cuda_runtime.h>
#include <cuda_bf16.h>

#define CDIM 1024
#define TT   2048
#define BB   4
#define NH   16
#define HD   64
#define MROWS 8192          // BB*TT
#define NQKV  3072

// ---------------- scratch (__device__ globals; allocation-free rule) --------
__device__ __align__(16) __nv_bfloat16 g_Xh[(size_t)MROWS*CDIM];
__device__ __align__(16) __nv_bfloat16 g_Xl[(size_t)MROWS*CDIM];
__device__ __align__(16) __nv_bfloat16 g_WQh[(size_t)NQKV*CDIM];
__device__ __align__(16) __nv_bfloat16 g_WQl[(size_t)NQKV*CDIM];
__device__ __align__(16) __nv_bfloat16 g_WPh[(size_t)CDIM*CDIM];
__device__ __align__(16) __nv_bfloat16 g_WPl[(size_t)CDIM*CDIM];
__device__ __align__(16) __nv_bfloat16 g_Qh[(size_t)BB*NH*TT*HD];
__device__ __align__(16) __nv_bfloat16 g_Ql[(size_t)BB*NH*TT*HD];
__device__ __align__(16) __nv_bfloat16 g_Kh[(size_t)BB*NH*TT*HD];
__device__ __align__(16) __nv_bfloat16 g_Kl[(size_t)BB*NH*TT*HD];
__device__ __align__(16) __nv_bfloat16 g_Vh[(size_t)BB*NH*TT*HD];
__device__ __align__(16) __nv_bfloat16 g_Vl[(size_t)BB*NH*TT*HD];
__device__ __align__(16) __nv_bfloat16 g_Ch[(size_t)MROWS*CDIM];
__device__ __align__(16) __nv_bfloat16 g_Cl[(size_t)MROWS*CDIM];

// ---------------- helpers ---------------------------------------------------
__device__ __forceinline__ void mma16816(float* c, const unsigned* a, const unsigned* b)
{
    asm volatile(
        "mma.sync.aligned.m16n8k16.row.col.f32.bf16.bf16.f32 "
        "{%0,%1,%2,%3}, {%4,%5,%6,%7}, {%8,%9}, {%0,%1,%2,%3};\n"
        : "+f"(c[0]), "+f"(c[1]), "+f"(c[2]), "+f"(c[3])
        : "r"(a[0]), "r"(a[1]), "r"(a[2]), "r"(a[3]), "r"(b[0]), "r"(b[1]));
}

// pack two floats into bf16x2 hi part, return lo-residual pack via out param
__device__ __forceinline__ unsigned pack_hl(float a, float b, unsigned& lo)
{
    __nv_bfloat162 h = __floats2bfloat162_rn(a, b);
    float ra = a - __bfloat162float(h.x);
    float rb = b - __bfloat162float(h.y);
    __nv_bfloat162 l = __floats2bfloat162_rn(ra, rb);
    lo = *reinterpret_cast<unsigned*>(&l);
    return *reinterpret_cast<unsigned*>(&h);
}

// ---------------- split fp32 -> (hi, lo) bf16 -------------------------------
__global__ __launch_bounds__(256)
void split_kernel(const float* __restrict__ src, __nv_bfloat16* __restrict__ hi,
                  __nv_bfloat16* __restrict__ lo, int n4)
{
    int i = blockIdx.x * 256 + threadIdx.x;
    if (i >= n4) return;
    float4 v = ((const float4*)src)[i];
    unsigned l0, l1;
    unsigned h0 = pack_hl(v.x, v.y, l0);
    unsigned h1 = pack_hl(v.z, v.w, l1);
    ((uint2*)hi)[i] = make_uint2(h0, h1);
    ((uint2*)lo)[i] = make_uint2(l0, l1);
}

// ---------------- GEMM: C[m,n] = sum_k A[m,k]*W[n,k]  (bf16x3, mma.sync) ----
// MODE 0: A=Xh/Xl, W=WQh/WQl, N=3072; epilogue: split+scatter -> Q/K/V hi/lo
// MODE 1: A=Ch/Cl,  W=WPh/WPl, N=1024; epilogue: fp32 to Cout
template<int MODE>
__global__ __launch_bounds__(256)
void gemm_mma_kernel(float* __restrict__ Cout)
{
    __shared__ __align__(16) __nv_bfloat16 Ahs[128][40];
    __shared__ __align__(16) __nv_bfloat16 Als[128][40];
    __shared__ __align__(16) __nv_bfloat16 Bhs[128][40];
    __shared__ __align__(16) __nv_bfloat16 Bls[128][40];

    const __nv_bfloat16* Ah = (MODE == 0) ? g_Xh  : g_Ch;
    const __nv_bfloat16* Al = (MODE == 0) ? g_Xl  : g_Cl;
    const __nv_bfloat16* Bh = (MODE == 0) ? g_WQh : g_WPh;
    const __nv_bfloat16* Bl = (MODE == 0) ? g_WQl : g_WPl;

    const int tid  = threadIdx.x;
    const int lane = tid & 31;
    const int wrp  = tid >> 5;          // 0..7
    const int g    = lane >> 2;         // 0..7
    const int tig  = lane & 3;          // 0..3
    const int wm   = wrp >> 2;          // 0..1 (64 rows each)
    const int wn   = wrp & 3;           // 0..3 (32 cols each)
    const int m0   = blockIdx.y * 128;
    const int n0   = blockIdx.x * 128;

    float acc[4][4][4];
    #pragma unroll
    for (int a = 0; a < 4; a++)
        #pragma unroll
        for (int b = 0; b < 4; b++)
            #pragma unroll
            for (int c = 0; c < 4; c++) acc[a][b][c] = 0.f;

    for (int kt = 0; kt < CDIM; kt += 32) {
        __syncthreads();
        #pragma unroll
        for (int r = 0; r < 2; r++) {
            int c   = tid + r * 256;      // 512 16B-chunks per array (128 rows x 4)
            int row = c >> 2, c4 = c & 3;
            size_t ga = (size_t)(m0 + row) * CDIM + kt + c4 * 8;
            size_t gb = (size_t)(n0 + row) * CDIM + kt + c4 * 8;
            *(uint4*)&Ahs[row][c4 * 8] = *(const uint4*)(Ah + ga);
            *(uint4*)&Als[row][c4 * 8] = *(const uint4*)(Al + ga);
            *(uint4*)&Bhs[row][c4 * 8] = *(const uint4*)(Bh + gb);
            *(uint4*)&Bls[row][c4 * 8] = *(const uint4*)(Bl + gb);
        }
        __syncthreads();

        #pragma unroll
        for (int kk = 0; kk < 32; kk += 16) {
            unsigned afh[4][4], afl[4][4], bfh[4][2], bfl[4][2];
            #pragma unroll
            for (int mt = 0; mt < 4; mt++) {
                int r0 = wm * 64 + mt * 16 + g;
                afh[mt][0] = *(const unsigned*)&Ahs[r0    ][kk + 2*tig];
                afh[mt][1] = *(const unsigned*)&Ahs[r0 + 8][kk + 2*tig];
                afh[mt][2] = *(const unsigned*)&Ahs[r0    ][kk + 2*tig + 8];
                afh[mt][3] = *(const unsigned*)&Ahs[r0 + 8][kk + 2*tig + 8];
                afl[mt][0] = *(const unsigned*)&Als[r0    ][kk + 2*tig];
                afl[mt][1] = *(const unsigned*)&Als[r0 + 8][kk + 2*tig];
                afl[mt][2] = *(const unsigned*)&Als[r0    ][kk + 2*tig + 8];
                afl[mt][3] = *(const unsigned*)&Als[r0 + 8][kk + 2*tig + 8];
            }
            #pragma unroll
            for (int nt = 0; nt < 4; nt++) {
                int rb = wn * 32 + nt * 8 + g;
                bfh[nt][0] = *(const unsigned*)&Bhs[rb][kk + 2*tig];
                bfh[nt][1] = *(const unsigned*)&Bhs[rb][kk + 2*tig + 8];
                bfl[nt][0] = *(const unsigned*)&Bls[rb][kk + 2*tig];
                bfl[nt][1] = *(const unsigned*)&Bls[rb][kk + 2*tig + 8];
            }
            #pragma unroll
            for (int mt = 0; mt < 4; mt++)
                #pragma unroll
                for (int nt = 0; nt < 4; nt++) {
                    mma16816(acc[mt][nt], afh[mt], bfh[nt]);
                    mma16816(acc[mt][nt], afh[mt], bfl[nt]);
                    mma16816(acc[mt][nt], afl[mt], bfh[nt]);
                }
        }
    }

    // ---------------- epilogue ----------------
    #pragma unroll
    for (int mt = 0; mt < 4; mt++) {
        int row = m0 + wm * 64 + mt * 16 + g;       // row g; row+8 for c2/c3
        #pragma unroll
        for (int nt = 0; nt < 4; nt++) {
            int n = n0 + wn * 32 + nt * 8 + 2 * tig;
            float v0 = acc[mt][nt][0], v1 = acc[mt][nt][1];
            float v2 = acc[mt][nt][2], v3 = acc[mt][nt][3];
            if (MODE == 1) {
                *(float2*)(Cout + (size_t)row * CDIM + n)       = make_float2(v0, v1);
                *(float2*)(Cout + (size_t)(row + 8) * CDIM + n) = make_float2(v2, v3);
            } else {
                int part = n >> 10;                 // 0=q 1=k 2=v
                int cc   = n & (CDIM - 1);
                int h    = cc >> 6;
                int d    = cc & 63;
                int b    = row >> 11;
                int t    = row & (TT - 1);
                if (part == 0) { v0 *= 0.125f; v1 *= 0.125f; v2 *= 0.125f; v3 *= 0.125f; }
                __nv_bfloat16* dh = (part == 0) ? g_Qh : (part == 1) ? g_Kh : g_Vh;
                __nv_bfloat16* dl = (part == 0) ? g_Ql : (part == 1) ? g_Kl : g_Vl;
                size_t base = (((size_t)(b * NH + h)) * TT + t) * HD + d;
                unsigned lp;
                unsigned hp = pack_hl(v0, v1, lp);
                *(unsigned*)(dh + base) = hp;  *(unsigned*)(dl + base) = lp;
                hp = pack_hl(v2, v3, lp);
                *(unsigned*)(dh + base + 8 * HD) = hp;  *(unsigned*)(dl + base + 8 * HD) = lp;
            }
        }
    }
}

// ---------------- causal flash attention (bf16x3 mma) -----------------------
// grid = (32 qtiles of 64 rows, 64 bh). block = 128 (4 warps, 16 q-rows each).
__global__ __launch_bounds__(128)
void attn_mma_kernel()
{
    __shared__ __align__(16) __nv_bfloat16 Khs[64][72];
    __shared__ __align__(16) __nv_bfloat16 Kls[64][72];
    __shared__ __align__(16) __nv_bfloat16 Vhs[64][72];
    __shared__ __align__(16) __nv_bfloat16 Vls[64][72];

    const int tid  = threadIdx.x;
    const int lane = tid & 31;
    const int wrp  = tid >> 5;                  // 0..3
    const int g    = lane >> 2;
    const int tig  = lane & 3;
    const int qt   = (int)gridDim.x - 1 - (int)blockIdx.x;   // heavy tiles first
    const int bh   = blockIdx.y;
    const int q0   = qt * 64;
    const int qg0  = q0 + 16 * wrp + g;
    const int qg1  = qg0 + 8;

    const size_t hb = (size_t)bh * TT * HD;

    // Q fragments (hi & lo) in registers, reused across all j-tiles
    unsigned qh[4][4], ql[4][4];
    {
        const __nv_bfloat16* Qhp = g_Qh + hb;
        const __nv_bfloat16* Qlp = g_Ql + hb;
        #pragma unroll
        for (int kt = 0; kt < 4; kt++) {
            size_t r0 = (size_t)qg0 * HD + 16 * kt + 2 * tig;
            size_t r1 = (size_t)qg1 * HD + 16 * kt + 2 * tig;
            qh[kt][0] = *(const unsigned*)(Qhp + r0);
            qh[kt][1] = *(const unsigned*)(Qhp + r1);
            qh[kt][2] = *(const unsigned*)(Qhp + r0 + 8);
            qh[kt][3] = *(const unsigned*)(Qhp + r1 + 8);
            ql[kt][0] = *(const unsigned*)(Qlp + r0);
            ql[kt][1] = *(const unsigned*)(Qlp + r1);
            ql[kt][2] = *(const unsigned*)(Qlp + r0 + 8);
            ql[kt][3] = *(const unsigned*)(Qlp + r1 + 8);
        }
    }

    float oacc[8][4];
    #pragma unroll
    for (int nt = 0; nt < 8; nt++)
        #pragma unroll
        for (int c = 0; c < 4; c++) oacc[nt][c] = 0.f;
    float m0r = -1e30f, m1r = -1e30f, l0r = 0.f, l1r = 0.f;

    for (int jt = 0; jt <= qt; jt++) {
        const int j0 = jt * 64;
        __syncthreads();
        // 64 rows x 64 bf16 = 512 16B-chunks per array; 128 threads x 4 reps.
        #pragma unroll
        for (int r = 0; r < 4; r++) {
            int c   = tid + r * 128;            // 0..511
            int row = c >> 3, c4 = c & 7;       // 8 chunks per 64-col row
            size_t go = hb + (size_t)(j0 + row) * HD + c4 * 8;
            *(uint4*)&Khs[row][c4 * 8] = *(const uint4*)(g_Kh + go);
            *(uint4*)&Kls[row][c4 * 8] = *(const uint4*)(g_Kl + go);
            *(uint4*)&Vhs[row][c4 * 8] = *(const uint4*)(g_Vh + go);
            *(uint4*)&Vls[row][c4 * 8] = *(const uint4*)(g_Vl + go);
        }
        __syncthreads();

        // ---- S = Q K^T (3-pass hi/lo) ----
        float sacc[8][4];
        #pragma unroll
        for (int nt = 0; nt < 8; nt++)
            #pragma unroll
            for (int c = 0; c < 4; c++) sacc[nt][c] = 0.f;

        #pragma unroll
        for (int kt = 0; kt < 4; kt++) {
            #pragma unroll
            for (int nt = 0; nt < 8; nt++) {
                unsigned bh2[2], bl2[2];
                bh2[0] = *(const unsigned*)&Khs[8*nt + g][16*kt + 2*tig];
                bh2[1] = *(const unsigned*)&Khs[8*nt + g][16*kt + 2*tig + 8];
                bl2[0] = *(const unsigned*)&Kls[8*nt + g][16*kt + 2*tig];
                bl2[1] = *(const unsigned*)&Kls[8*nt + g][16*kt + 2*tig + 8];
                mma16816(sacc[nt], qh[kt], bh2);
                mma16816(sacc[nt], qh[kt], bl2);
                mma16816(sacc[nt], ql[kt], bh2);
            }
        }

        // ---- causal mask on diagonal tile ----
        if (jt == qt) {
            #pragma unroll
            for (int nt = 0; nt < 8; nt++) {
                int jg = j0 + 8 * nt + 2 * tig;
                if (jg     > qg0) sacc[nt][0] = -1e30f;
                if (jg + 1 > qg0) sacc[nt][1] = -1e30f;
                if (jg     > qg1) sacc[nt][2] = -1e30f;
                if (jg + 1 > qg1) sacc[nt][3] = -1e30f;
            }
        }

        // ---- online softmax (per-row, quad shuffles) ----
        float t0 = -1e30f, t1 = -1e30f;
        #pragma unroll
        for (int nt = 0; nt < 8; nt++) {
            t0 = fmaxf(t0, fmaxf(sacc[nt][0], sacc[nt][1]));
            t1 = fmaxf(t1, fmaxf(sacc[nt][2], sacc[nt][3]));
        }
        t0 = fmaxf(t0, __shfl_xor_sync(0xffffffffu, t0, 1));
        t0 = fmaxf(t0, __shfl_xor_sync(0xffffffffu, t0, 2));
        t1 = fmaxf(t1, __shfl_xor_sync(0xffffffffu, t1, 1));
        t1 = fmaxf(t1, __shfl_xor_sync(0xffffffffu, t1, 2));
        float mn0 = fmaxf(m0r, t0), mn1 = fmaxf(m1r, t1);
        float al0 = __expf(m0r - mn0), al1 = __expf(m1r - mn1);
        m0r = mn0; m1r = mn1;
        #pragma unroll
        for (int nt = 0; nt < 8; nt++) {
            oacc[nt][0] *= al0; oacc[nt][1] *= al0;
            oacc[nt][2] *= al1; oacc[nt][3] *= al1;
        }

        // ---- P = exp(S-m): build A-fragments in-register (hi & lo) ----
        unsigned ph[4][4], pl[4][4];
        float rs0 = 0.f, rs1 = 0.f;
        #pragma unroll
        for (int kt = 0; kt < 4; kt++) {
            float p00 = __expf(sacc[2*kt    ][0] - mn0);
            float p01 = __expf(sacc[2*kt    ][1] - mn0);
            float p02 = __expf(sacc[2*kt    ][2] - mn1);
            float p03 = __expf(sacc[2*kt    ][3] - mn1);
            float p10 = __expf(sacc[2*kt + 1][0] - mn0);
            float p11 = __expf(sacc[2*kt + 1][1] - mn0);
            float p12 = __expf(sacc[2*kt + 1][2] - mn1);
            float p13 = __expf(sacc[2*kt + 1][3] - mn1);
            rs0 += (p00 + p01) + (p10 + p11);
            rs1 += (p02 + p03) + (p12 + p13);
            ph[kt][0] = pack_hl(p00, p01, pl[kt][0]);
            ph[kt][1] = pack_hl(p02, p03, pl[kt][1]);
            ph[kt][2] = pack_hl(p10, p11, pl[kt][2]);
            ph[kt][3] = pack_hl(p12, p13, pl[kt][3]);
        }
        rs0 += __shfl_xor_sync(0xffffffffu, rs0, 1);
        rs0 += __shfl_xor_sync(0xffffffffu, rs0, 2);
        rs1 += __shfl_xor_sync(0xffffffffu, rs1, 1);
        rs1 += __shfl_xor_sync(0xffffffffu, rs1, 2);
        l0r = l0r * al0 + rs0;
        l1r = l1r * al1 + rs1;

        // ---- O += P @ V  (3-pass hi/lo; V B-frags via ldmatrix.trans) ----
        #pragma unroll
        for (int kt = 0; kt < 4; kt++) {
            int vrow = 16 * kt + (lane & 15);
            #pragma unroll
            for (int nt = 0; nt < 8; nt++) {
                unsigned vbh[2], vbl[2];
                unsigned ah_ = (unsigned)__cvta_generic_to_shared(&Vhs[vrow][8 * nt]);
                unsigned al_ = (unsigned)__cvta_generic_to_shared(&Vls[vrow][8 * nt]);
                asm volatile("ldmatrix.sync.aligned.m8n8.x2.trans.shared.b16 {%0,%1}, [%2];"
                             : "=r"(vbh[0]), "=r"(vbh[1]) : "r"(ah_));
                asm volatile("ldmatrix.sync.aligned.m8n8.x2.trans.shared.b16 {%0,%1}, [%2];"
                             : "=r"(vbl[0]), "=r"(vbl[1]) : "r"(al_));
                mma16816(oacc[nt], ph[kt], vbh);
                mma16816(oacc[nt], ph[kt], vbl);
                mma16816(oacc[nt], pl[kt], vbh);
            }
        }
    }

    // ---- epilogue: O/l -> Ctx hi/lo bf16 [b, t, h*64+d] ----
    const float inv0 = 1.0f / l0r, inv1 = 1.0f / l1r;
    const int b = bh >> 4, h = bh & 15;
    size_t crow0 = ((size_t)(b * TT + qg0)) * CDIM + h * HD;
    size_t crow1 = ((size_t)(b * TT + qg1)) * CDIM + h * HD;
    #pragma unroll
    for (int nt = 0; nt < 8; nt++) {
        int d = 8 * nt + 2 * tig;
        unsigned lp;
        unsigned hp = pack_hl(oacc[nt][0] * inv0, oacc[nt][1] * inv0, lp);
        *(unsigned*)(g_Ch + crow0 + d) = hp;  *(unsigned*)(g_Cl + crow0 + d) = lp;
        hp = pack_hl(oacc[nt][2] * inv1, oacc[nt][3] * inv1, lp);
        *(unsigned*)(g_Ch + crow1 + d) = hp;  *(unsigned*)(g_Cl + crow1 + d) = lp;
    }
}

// ---------------------------------------------------------------------------
extern "C" void kernel_launch(void* const* d_in, const int* in_sizes, int n_in,
                              void* d_out, int out_size)
{
    const float* x      = (const float*)d_in[0];  // [4,2048,1024]
    const float* w_qkv  = (const float*)d_in[1];  // [3072,1024]
    const float* w_proj = (const float*)d_in[2];  // [1024,1024]
    float* out = (float*)d_out;                   // [4,2048,1024] fp32

    __nv_bfloat16 *xh, *xl, *wqh, *wql, *wph, *wpl;
    cudaGetSymbolAddress((void**)&xh,  g_Xh);  cudaGetSymbolAddress((void**)&xl,  g_Xl);
    cudaGetSymbolAddress((void**)&wqh, g_WQh); cudaGetSymbolAddress((void**)&wql, g_WQl);
    cudaGetSymbolAddress((void**)&wph, g_WPh); cudaGetSymbolAddress((void**)&wpl, g_WPl);

    // 1) split inputs/weights to bf16 hi/lo
    split_kernel<<<(MROWS*CDIM/4 + 255)/256, 256>>>(x,      xh,  xl,  MROWS*CDIM/4);
    split_kernel<<<(NQKV*CDIM/4  + 255)/256, 256>>>(w_qkv,  wqh, wql, NQKV*CDIM/4);
    split_kernel<<<(CDIM*CDIM/4  + 255)/256, 256>>>(w_proj, wph, wpl, CDIM*CDIM/4);

    // 2) QKV projection (tensor cores) -> Q/K/V hi/lo [bh,T,64], Q pre-scaled
    gemm_mma_kernel<0><<<dim3(NQKV/128, MROWS/128), 256>>>(nullptr);

    // 3) causal flash attention (tensor cores) -> Ctx hi/lo
    attn_mma_kernel<<<dim3(TT/64, BB*NH), 128>>>();

    // 4) output projection (tensor cores) -> fp32 out
    gemm_mma_kernel<1><<<dim3(CDIM/128, MROWS/128), 256>>>(out);
}

// round 8
// speedup vs baseline: 2.8749x; 1.7322x over previous
#include <cuda_runtime.h>
#include <cuda_bf16.h>

#define CDIM 1024
#define TT   2048
#define BB   4
#define NH   16
#define HD   64
#define MROWS 8192          // BB*TT
#define NQKV  3072

// ---------------- scratch (__device__ globals; allocation-free rule) --------
__device__ __align__(16) __nv_bfloat16 g_Xh[(size_t)MROWS*CDIM];
__device__ __align__(16) __nv_bfloat16 g_Xl[(size_t)MROWS*CDIM];
__device__ __align__(16) __nv_bfloat16 g_WQh[(size_t)NQKV*CDIM];
__device__ __align__(16) __nv_bfloat16 g_WQl[(size_t)NQKV*CDIM];
__device__ __align__(16) __nv_bfloat16 g_WPh[(size_t)CDIM*CDIM];
__device__ __align__(16) __nv_bfloat16 g_WPl[(size_t)CDIM*CDIM];
__device__ __align__(16) __nv_bfloat16 g_Qh[(size_t)BB*NH*TT*HD];
__device__ __align__(16) __nv_bfloat16 g_Ql[(size_t)BB*NH*TT*HD];
__device__ __align__(16) __nv_bfloat16 g_Kh[(size_t)BB*NH*TT*HD];
__device__ __align__(16) __nv_bfloat16 g_Kl[(size_t)BB*NH*TT*HD];
__device__ __align__(16) __nv_bfloat16 g_Vh[(size_t)BB*NH*TT*HD];
__device__ __align__(16) __nv_bfloat16 g_Vl[(size_t)BB*NH*TT*HD];
__device__ __align__(16) __nv_bfloat16 g_Ch[(size_t)MROWS*CDIM];
__device__ __align__(16) __nv_bfloat16 g_Cl[(size_t)MROWS*CDIM];

// ---------------- helpers ---------------------------------------------------
__device__ __forceinline__ void mma16816(float* c, const unsigned* a, const unsigned* b)
{
    asm volatile(
        "mma.sync.aligned.m16n8k16.row.col.f32.bf16.bf16.f32 "
        "{%0,%1,%2,%3}, {%4,%5,%6,%7}, {%8,%9}, {%0,%1,%2,%3};\n"
        : "+f"(c[0]), "+f"(c[1]), "+f"(c[2]), "+f"(c[3])
        : "r"(a[0]), "r"(a[1]), "r"(a[2]), "r"(a[3]), "r"(b[0]), "r"(b[1]));
}

#define LDSM4(rg, addr) \
    asm volatile("ldmatrix.sync.aligned.m8n8.x4.shared.b16 {%0,%1,%2,%3}, [%4];" \
                 : "=r"((rg)[0]), "=r"((rg)[1]), "=r"((rg)[2]), "=r"((rg)[3]) : "r"(addr))
#define LDSM2(rg, addr) \
    asm volatile("ldmatrix.sync.aligned.m8n8.x2.shared.b16 {%0,%1}, [%2];" \
                 : "=r"((rg)[0]), "=r"((rg)[1]) : "r"(addr))
#define LDSM2T(rg, addr) \
    asm volatile("ldmatrix.sync.aligned.m8n8.x2.trans.shared.b16 {%0,%1}, [%2];" \
                 : "=r"((rg)[0]), "=r"((rg)[1]) : "r"(addr))
#define CP16(dst, src) \
    asm volatile("cp.async.cg.shared.global [%0], [%1], 16;" :: "r"(dst), "l"(src))
#define CP_COMMIT() asm volatile("cp.async.commit_group;" ::: "memory")

// pack two floats into bf16x2 hi part, return lo-residual pack via out param
__device__ __forceinline__ unsigned pack_hl(float a, float b, unsigned& lo)
{
    __nv_bfloat162 h = __floats2bfloat162_rn(a, b);
    float ra = a - __bfloat162float(h.x);
    float rb = b - __bfloat162float(h.y);
    __nv_bfloat162 l = __floats2bfloat162_rn(ra, rb);
    lo = *reinterpret_cast<unsigned*>(&l);
    return *reinterpret_cast<unsigned*>(&h);
}

// ---------------- split fp32 -> (hi, lo) bf16 -------------------------------
__global__ __launch_bounds__(256)
void split_kernel(const float* __restrict__ src, __nv_bfloat16* __restrict__ hi,
                  __nv_bfloat16* __restrict__ lo, int n4)
{
    int i = blockIdx.x * 256 + threadIdx.x;
    if (i >= n4) return;
    float4 v = ((const float4*)src)[i];
    unsigned l0, l1;
    unsigned h0 = pack_hl(v.x, v.y, l0);
    unsigned h1 = pack_hl(v.z, v.w, l1);
    ((uint2*)hi)[i] = make_uint2(h0, h1);
    ((uint2*)lo)[i] = make_uint2(l0, l1);
}

// ---------------- GEMM: C[m,n] = sum_k A[m,k]*W[n,k]  (bf16x3, mma.sync) ----
// 128x128x32 tile, 256 threads, cp.async 2-stage pipeline, ldmatrix frags.
// Dynamic smem: 2 stages x {Ah,Al,Bh,Bl}[128][40] bf16 = 81920 B.
// Stage element layout: Ah @0, Al @5120, Bh @10240, Bl @15360; stage stride 20480.
#define GSTG 20480
#define QSCALE 0.18033688f   // 0.125 * log2(e): folds softmax base-2 into Q

template<int MODE>
__device__ __forceinline__ void gemm_load_tile(
    unsigned sb, int so,
    const __nv_bfloat16* Ah, const __nv_bfloat16* Al,
    const __nv_bfloat16* Bh, const __nv_bfloat16* Bl,
    int m0, int n0, int kt, int tid)
{
    #pragma unroll
    for (int r = 0; r < 2; r++) {
        int c = tid + r * 256;          // 512 16B-chunks (128 rows x 4)
        int row = c >> 2, c4 = c & 3;
        size_t ga = (size_t)(m0 + row) * CDIM + kt + c4 * 8;
        size_t gb = (size_t)(n0 + row) * CDIM + kt + c4 * 8;
        unsigned d = sb + 2u * (so + row * 40 + c4 * 8);
        CP16(d,               Ah + ga);
        CP16(d + 2u * 5120,   Al + ga);
        CP16(d + 2u * 10240,  Bh + gb);
        CP16(d + 2u * 15360,  Bl + gb);
    }
    CP_COMMIT();
}

template<int MODE>
__global__ __launch_bounds__(256)
void gemm_mma_kernel(float* __restrict__ Cout)
{
    extern __shared__ __nv_bfloat16 dsm[];
    const unsigned sb = (unsigned)__cvta_generic_to_shared(dsm);

    const __nv_bfloat16* Ah = (MODE == 0) ? g_Xh  : g_Ch;
    const __nv_bfloat16* Al = (MODE == 0) ? g_Xl  : g_Cl;
    const __nv_bfloat16* Bh = (MODE == 0) ? g_WQh : g_WPh;
    const __nv_bfloat16* Bl = (MODE == 0) ? g_WQl : g_WPl;

    const int tid  = threadIdx.x;
    const int lane = tid & 31;
    const int wrp  = tid >> 5;          // 0..7
    const int g    = lane >> 2;         // 0..7
    const int tig  = lane & 3;          // 0..3
    const int wm   = wrp >> 2;          // 0..1 (64 rows each)
    const int wn   = wrp & 3;           // 0..3 (32 cols each)
    const int m0   = blockIdx.y * 128;
    const int n0   = blockIdx.x * 128;

    // ldmatrix per-lane row/col offsets (elements, within a stage array)
    const int a_off = (wm * 64 + (lane & 15)) * 40 + 8 * ((lane >> 4) & 1);
    const int b_off = (wn * 32 + (lane & 7)) * 40 + 8 * ((lane >> 3) & 1);

    float acc[4][4][4];
    #pragma unroll
    for (int a = 0; a < 4; a++)
        #pragma unroll
        for (int b = 0; b < 4; b++)
            #pragma unroll
            for (int c = 0; c < 4; c++) acc[a][b][c] = 0.f;

    gemm_load_tile<MODE>(sb, 0, Ah, Al, Bh, Bl, m0, n0, 0, tid);

    #pragma unroll 1
    for (int t = 0; t < CDIM / 32; t++) {
        if (t < CDIM / 32 - 1) {
            gemm_load_tile<MODE>(sb, ((t + 1) & 1) * GSTG, Ah, Al, Bh, Bl,
                                 m0, n0, (t + 1) * 32, tid);
            asm volatile("cp.async.wait_group 1;" ::: "memory");
        } else {
            asm volatile("cp.async.wait_group 0;" ::: "memory");
        }
        __syncthreads();

        const int so = (t & 1) * GSTG;
        #pragma unroll
        for (int kk = 0; kk < 32; kk += 16) {
            unsigned afh[4][4], afl[4][4], bfh[4][2], bfl[4][2];
            #pragma unroll
            for (int mt = 0; mt < 4; mt++) {
                unsigned aaddr = sb + 2u * (so + a_off + mt * 640 + kk);
                LDSM4(afh[mt], aaddr);
                LDSM4(afl[mt], aaddr + 2u * 5120);
            }
            #pragma unroll
            for (int nt = 0; nt < 4; nt++) {
                unsigned baddr = sb + 2u * (so + 10240 + b_off + nt * 320 + kk);
                LDSM2(bfh[nt], baddr);
                LDSM2(bfl[nt], baddr + 2u * 5120);
            }
            // pass-outer: 16 independent MMAs between accumulator reuse
            #pragma unroll
            for (int mt = 0; mt < 4; mt++)
                #pragma unroll
                for (int nt = 0; nt < 4; nt++)
                    mma16816(acc[mt][nt], afh[mt], bfh[nt]);
            #pragma unroll
            for (int mt = 0; mt < 4; mt++)
                #pragma unroll
                for (int nt = 0; nt < 4; nt++)
                    mma16816(acc[mt][nt], afh[mt], bfl[nt]);
            #pragma unroll
            for (int mt = 0; mt < 4; mt++)
                #pragma unroll
                for (int nt = 0; nt < 4; nt++)
                    mma16816(acc[mt][nt], afl[mt], bfh[nt]);
        }
        __syncthreads();
    }

    // ---------------- epilogue ----------------
    #pragma unroll
    for (int mt = 0; mt < 4; mt++) {
        int row = m0 + wm * 64 + mt * 16 + g;       // row g; row+8 for c2/c3
        #pragma unroll
        for (int nt = 0; nt < 4; nt++) {
            int n = n0 + wn * 32 + nt * 8 + 2 * tig;
            float v0 = acc[mt][nt][0], v1 = acc[mt][nt][1];
            float v2 = acc[mt][nt][2], v3 = acc[mt][nt][3];
            if (MODE == 1) {
                *(float2*)(Cout + (size_t)row * CDIM + n)       = make_float2(v0, v1);
                *(float2*)(Cout + (size_t)(row + 8) * CDIM + n) = make_float2(v2, v3);
            } else {
                int part = n >> 10;                 // 0=q 1=k 2=v
                int cc   = n & (CDIM - 1);
                int h    = cc >> 6;
                int d    = cc & 63;
                int b    = row >> 11;
                int tq   = row & (TT - 1);
                if (part == 0) { v0 *= QSCALE; v1 *= QSCALE; v2 *= QSCALE; v3 *= QSCALE; }
                __nv_bfloat16* dh = (part == 0) ? g_Qh : (part == 1) ? g_Kh : g_Vh;
                __nv_bfloat16* dl = (part == 0) ? g_Ql : (part == 1) ? g_Kl : g_Vl;
                size_t base = (((size_t)(b * NH + h)) * TT + tq) * HD + d;
                unsigned lp;
                unsigned hp = pack_hl(v0, v1, lp);
                *(unsigned*)(dh + base) = hp;  *(unsigned*)(dl + base) = lp;
                hp = pack_hl(v2, v3, lp);
                *(unsigned*)(dh + base + 8 * HD) = hp;  *(unsigned*)(dl + base + 8 * HD) = lp;
            }
        }
    }
}

// ---------------- causal flash attention (bf16x3 mma) -----------------------
// grid = (16 qtiles of 128 rows, 64 bh). 256 threads (8 warps, 16 q-rows each).
// Q is pre-scaled by 0.125*log2e -> softmax uses exp2f (base-2, exactly equal).
__global__ __launch_bounds__(256)
void attn_mma_kernel()
{
    __shared__ __align__(16) __nv_bfloat16 Khs[64][72];
    __shared__ __align__(16) __nv_bfloat16 Kls[64][72];
    __shared__ __align__(16) __nv_bfloat16 Vhs[64][72];
    __shared__ __align__(16) __nv_bfloat16 Vls[64][72];

    const int tid  = threadIdx.x;
    const int lane = tid & 31;
    const int wrp  = tid >> 5;                  // 0..7
    const int g    = lane >> 2;
    const int tig  = lane & 3;
    const int qt   = (int)gridDim.x - 1 - (int)blockIdx.x;   // heavy tiles first
    const int bh   = blockIdx.y;
    const int qg0  = qt * 128 + 16 * wrp + g;
    const int qg1  = qg0 + 8;

    const size_t hb = (size_t)bh * TT * HD;

    // ldmatrix per-lane offset for K-fragments (elements, row stride 72)
    const int k_off = (lane & 7) * 72 + 8 * ((lane >> 3) & 1);
    const unsigned khs_b = (unsigned)__cvta_generic_to_shared(&Khs[0][0]);
    const unsigned kls_b = (unsigned)__cvta_generic_to_shared(&Kls[0][0]);

    // Q fragments (hi & lo) in registers, reused across all j-tiles
    unsigned qh[4][4], ql[4][4];
    {
        const __nv_bfloat16* Qhp = g_Qh + hb;
        const __nv_bfloat16* Qlp = g_Ql + hb;
        #pragma unroll
        for (int kt = 0; kt < 4; kt++) {
            size_t r0 = (size_t)qg0 * HD + 16 * kt + 2 * tig;
            size_t r1 = (size_t)qg1 * HD + 16 * kt + 2 * tig;
            qh[kt][0] = *(const unsigned*)(Qhp + r0);
            qh[kt][1] = *(const unsigned*)(Qhp + r1);
            qh[kt][2] = *(const unsigned*)(Qhp + r0 + 8);
            qh[kt][3] = *(const unsigned*)(Qhp + r1 + 8);
            ql[kt][0] = *(const unsigned*)(Qlp + r0);
            ql[kt][1] = *(const unsigned*)(Qlp + r1);
            ql[kt][2] = *(const unsigned*)(Qlp + r0 + 8);
            ql[kt][3] = *(const unsigned*)(Qlp + r1 + 8);
        }
    }

    float oacc[8][4];
    #pragma unroll
    for (int nt = 0; nt < 8; nt++)
        #pragma unroll
        for (int c = 0; c < 4; c++) oacc[nt][c] = 0.f;
    float m0r = -1e30f, m1r = -1e30f, l0r = 0.f, l1r = 0.f;

    const int ntiles = 2 * qt + 2;
    for (int jt = 0; jt < ntiles; jt++) {
        const int j0 = jt * 64;
        __syncthreads();
        // 64 rows x 64 bf16 = 512 16B-chunks per array; 256 threads x 2 reps.
        #pragma unroll
        for (int r = 0; r < 2; r++) {
            int c   = tid + r * 256;            // 0..511
            int row = c >> 3, c4 = c & 7;       // 8 chunks per 64-col row
            size_t go = hb + (size_t)(j0 + row) * HD + c4 * 8;
            *(uint4*)&Khs[row][c4 * 8] = *(const uint4*)(g_Kh + go);
            *(uint4*)&Kls[row][c4 * 8] = *(const uint4*)(g_Kl + go);
            *(uint4*)&Vhs[row][c4 * 8] = *(const uint4*)(g_Vh + go);
            *(uint4*)&Vls[row][c4 * 8] = *(const uint4*)(g_Vl + go);
        }
        __syncthreads();

        // ---- S = Q K^T (3-pass hi/lo, pass-outer per kt) ----
        float sacc[8][4];
        #pragma unroll
        for (int nt = 0; nt < 8; nt++)
            #pragma unroll
            for (int c = 0; c < 4; c++) sacc[nt][c] = 0.f;

        #pragma unroll
        for (int kt = 0; kt < 4; kt++) {
            unsigned khf[8][2], klf[8][2];
            #pragma unroll
            for (int nt = 0; nt < 8; nt++) {
                unsigned a = 2u * (k_off + nt * 576 + 16 * kt);
                LDSM2(khf[nt], khs_b + a);
                LDSM2(klf[nt], kls_b + a);
            }
            #pragma unroll
            for (int nt = 0; nt < 8; nt++) mma16816(sacc[nt], qh[kt], khf[nt]);
            #pragma unroll
            for (int nt = 0; nt < 8; nt++) mma16816(sacc[nt], qh[kt], klf[nt]);
            #pragma unroll
            for (int nt = 0; nt < 8; nt++) mma16816(sacc[nt], ql[kt], khf[nt]);
        }

        // ---- causal mask (only tiles that can touch the diagonal) ----
        if (j0 + 63 > qt * 128 + 16 * wrp) {
            #pragma unroll
            for (int nt = 0; nt < 8; nt++) {
                int jg = j0 + 8 * nt + 2 * tig;
                if (jg     > qg0) sacc[nt][0] = -1e30f;
                if (jg + 1 > qg0) sacc[nt][1] = -1e30f;
                if (jg     > qg1) sacc[nt][2] = -1e30f;
                if (jg + 1 > qg1) sacc[nt][3] = -1e30f;
            }
        }

        // ---- online softmax (base-2; per-row, quad shuffles) ----
        float t0 = -1e30f, t1 = -1e30f;
        #pragma unroll
        for (int nt = 0; nt < 8; nt++) {
            t0 = fmaxf(t0, fmaxf(sacc[nt][0], sacc[nt][1]));
            t1 = fmaxf(t1, fmaxf(sacc[nt][2], sacc[nt][3]));
        }
        t0 = fmaxf(t0, __shfl_xor_sync(0xffffffffu, t0, 1));
        t0 = fmaxf(t0, __shfl_xor_sync(0xffffffffu, t0, 2));
        t1 = fmaxf(t1, __shfl_xor_sync(0xffffffffu, t1, 1));
        t1 = fmaxf(t1, __shfl_xor_sync(0xffffffffu, t1, 2));
        float mn0 = fmaxf(m0r, t0), mn1 = fmaxf(m1r, t1);
        float al0 = exp2f(m0r - mn0), al1 = exp2f(m1r - mn1);
        m0r = mn0; m1r = mn1;
        #pragma unroll
        for (int nt = 0; nt < 8; nt++) {
            oacc[nt][0] *= al0; oacc[nt][1] *= al0;
            oacc[nt][2] *= al1; oacc[nt][3] *= al1;
        }

        // ---- P = exp2(S-m): build A-fragments in-register (hi & lo) ----
        unsigned ph[4][4], pl[4][4];
        float rs0 = 0.f, rs1 = 0.f;
        #pragma unroll
        for (int kt = 0; kt < 4; kt++) {
            float p00 = exp2f(sacc[2*kt    ][0] - mn0);
            float p01 = exp2f(sacc[2*kt    ][1] - mn0);
            float p02 = exp2f(sacc[2*kt    ][2] - mn1);
            float p03 = exp2f(sacc[2*kt    ][3] - mn1);
            float p10 = exp2f(sacc[2*kt + 1][0] - mn0);
            float p11 = exp2f(sacc[2*kt + 1][1] - mn0);
            float p12 = exp2f(sacc[2*kt + 1][2] - mn1);
            float p13 = exp2f(sacc[2*kt + 1][3] - mn1);
            rs0 += (p00 + p01) + (p10 + p11);
            rs1 += (p02 + p03) + (p12 + p13);
            ph[kt][0] = pack_hl(p00, p01, pl[kt][0]);
            ph[kt][1] = pack_hl(p02, p03, pl[kt][1]);
            ph[kt][2] = pack_hl(p10, p11, pl[kt][2]);
            ph[kt][3] = pack_hl(p12, p13, pl[kt][3]);
        }
        rs0 += __shfl_xor_sync(0xffffffffu, rs0, 1);
        rs0 += __shfl_xor_sync(0xffffffffu, rs0, 2);
        rs1 += __shfl_xor_sync(0xffffffffu, rs1, 1);
        rs1 += __shfl_xor_sync(0xffffffffu, rs1, 2);
        l0r = l0r * al0 + rs0;
        l1r = l1r * al1 + rs1;

        // ---- O += P @ V  (3-pass hi/lo, pass-outer per kt) ----
        #pragma unroll
        for (int kt = 0; kt < 4; kt++) {
            unsigned vbh[8][2], vbl[8][2];
            int vrow = 16 * kt + (lane & 15);
            #pragma unroll
            for (int nt = 0; nt < 8; nt++) {
                LDSM2T(vbh[nt], (unsigned)__cvta_generic_to_shared(&Vhs[vrow][8 * nt]));
                LDSM2T(vbl[nt], (unsigned)__cvta_generic_to_shared(&Vls[vrow][8 * nt]));
            }
            #pragma unroll
            for (int nt = 0; nt < 8; nt++) mma16816(oacc[nt], ph[kt], vbh[nt]);
            #pragma unroll
            for (int nt = 0; nt < 8; nt++) mma16816(oacc[nt], ph[kt], vbl[nt]);
            #pragma unroll
            for (int nt = 0; nt < 8; nt++) mma16816(oacc[nt], pl[kt], vbh[nt]);
        }
    }

    // ---- epilogue: O/l -> Ctx hi/lo bf16 [b, t, h*64+d] ----
    const float inv0 = 1.0f / l0r, inv1 = 1.0f / l1r;
    const int b = bh >> 4, h = bh & 15;
    size_t crow0 = ((size_t)(b * TT + qg0)) * CDIM + h * HD;
    size_t crow1 = ((size_t)(b * TT + qg1)) * CDIM + h * HD;
    #pragma unroll
    for (int nt = 0; nt < 8; nt++) {
        int d = 8 * nt + 2 * tig;
        unsigned lp;
        unsigned hp = pack_hl(oacc[nt][0] * inv0, oacc[nt][1] * inv0, lp);
        *(unsigned*)(g_Ch + crow0 + d) = hp;  *(unsigned*)(g_Cl + crow0 + d) = lp;
        hp = pack_hl(oacc[nt][2] * inv1, oacc[nt][3] * inv1, lp);
        *(unsigned*)(g_Ch + crow1 + d) = hp;  *(unsigned*)(g_Cl + crow1 + d) = lp;
    }
}

// ---------------------------------------------------------------------------
extern "C" void kernel_launch(void* const* d_in, const int* in_sizes, int n_in,
                              void* d_out, int out_size)
{
    const float* x      = (const float*)d_in[0];  // [4,2048,1024]
    const float* w_qkv  = (const float*)d_in[1];  // [3072,1024]
    const float* w_proj = (const float*)d_in[2];  // [1024,1024]
    float* out = (float*)d_out;                   // [4,2048,1024] fp32

    __nv_bfloat16 *xh, *xl, *wqh, *wql, *wph, *wpl;
    cudaGetSymbolAddress((void**)&xh,  g_Xh);  cudaGetSymbolAddress((void**)&xl,  g_Xl);
    cudaGetSymbolAddress((void**)&wqh, g_WQh); cudaGetSymbolAddress((void**)&wql, g_WQl);
    cudaGetSymbolAddress((void**)&wph, g_WPh); cudaGetSymbolAddress((void**)&wpl, g_WPl);

    const int GEMM_SMEM = 2 * GSTG * 2;   // 81920 B
    cudaFuncSetAttribute(gemm_mma_kernel<0>,
                         cudaFuncAttributeMaxDynamicSharedMemorySize, GEMM_SMEM);
    cudaFuncSetAttribute(gemm_mma_kernel<1>,
                         cudaFuncAttributeMaxDynamicSharedMemorySize, GEMM_SMEM);

    // 1) split inputs/weights to bf16 hi/lo
    split_kernel<<<(MROWS*CDIM/4 + 255)/256, 256>>>(x,      xh,  xl,  MROWS*CDIM/4);
    split_kernel<<<(NQKV*CDIM/4  + 255)/256, 256>>>(w_qkv,  wqh, wql, NQKV*CDIM/4);
    split_kernel<<<(CDIM*CDIM/4  + 255)/256, 256>>>(w_proj, wph, wpl, CDIM*CDIM/4);

    // 2) QKV projection -> Q/K/V hi/lo [bh,T,64]; Q pre-scaled by 0.125*log2e
    gemm_mma_kernel<0><<<dim3(NQKV/128, MROWS/128), 256, GEMM_SMEM>>>(nullptr);

    // 3) causal flash attention -> Ctx hi/lo
    attn_mma_kernel<<<dim3(TT/128, BB*NH), 256>>>();

    // 4) output projection -> fp32 out
    gemm_mma_kernel<1><<<dim3(CDIM/128, MROWS/128), 256, GEMM_SMEM>>>(out);
}